// round 15
// baseline (speedup 1.0000x reference)
#include <cuda_runtime.h>
#include <cuda_bf16.h>
#include <math.h>
#include <stdint.h>

// Shapes (fixed by the problem)
// B=4, N=256, D=768, H=12, DD=64, HD=64, M = B*N = 1024
#define MROWS 1024
#define DMODEL 768
#define NSEQ 256
#define NHEAD 12
#define HDIM 64
#define DDIM 64

// ---------------- scratch (no allocations allowed) ----------------
__device__ float g_xn   [MROWS * DMODEL];
__device__ float g_qkv  [MROWS * 3 * DMODEL];
__device__ float g_s1   [MROWS * DMODEL];     // silu(xn@gate_w1+b1)
__device__ float g_gated[MROWS * DMODEL];
__device__ float g_biasT[4 * NHEAD * NSEQ * NSEQ];  // [b][h][i][j]
__device__ float g_ctx  [MROWS * DMODEL];
__device__ float g_a    [MROWS * DMODEL];     // ctx * sigmoid(gated)
__device__ float g_x2   [MROWS * DMODEL];
__device__ float g_y    [MROWS * DMODEL];
__device__ float g_ffh  [MROWS * 2 * DMODEL];

// ---------------- helpers ----------------
__device__ __forceinline__ float warp_sum(float v) {
    #pragma unroll
    for (int o = 16; o > 0; o >>= 1) v += __shfl_xor_sync(0xffffffffu, v, o);
    return v;
}
__device__ __forceinline__ float warp_max(float v) {
    #pragma unroll
    for (int o = 16; o > 0; o >>= 1) v = fmaxf(v, __shfl_xor_sync(0xffffffffu, v, o));
    return v;
}

// ---------------- LayerNorm: one block per row of 768 ----------------
__global__ __launch_bounds__(256) void ln_kernel(
    const float* __restrict__ x, const float* __restrict__ gw,
    const float* __restrict__ bw, float* __restrict__ out)
{
    int row = blockIdx.x;
    int tid = threadIdx.x;
    const float* xr = x + (size_t)row * DMODEL;
    float v0 = xr[tid], v1 = xr[tid + 256], v2 = xr[tid + 512];
    float s  = v0 + v1 + v2;
    float s2 = v0 * v0 + v1 * v1 + v2 * v2;
    __shared__ float sm[8], sm2[8], stat[2];
    float ws = warp_sum(s), ws2 = warp_sum(s2);
    int wid = tid >> 5, lane = tid & 31;
    if (!lane) { sm[wid] = ws; sm2[wid] = ws2; }
    __syncthreads();
    if (tid == 0) {
        float S = 0.f, S2 = 0.f;
        #pragma unroll
        for (int i = 0; i < 8; ++i) { S += sm[i]; S2 += sm2[i]; }
        float mu  = S * (1.f / DMODEL);
        float var = S2 * (1.f / DMODEL) - mu * mu;
        stat[0] = mu;
        stat[1] = rsqrtf(var + 1e-5f);
    }
    __syncthreads();
    float mu = stat[0], rstd = stat[1];
    float* orow = out + (size_t)row * DMODEL;
    orow[tid]       = (v0 - mu) * rstd * gw[tid]       + bw[tid];
    orow[tid + 256] = (v1 - mu) * rstd * gw[tid + 256] + bw[tid + 256];
    orow[tid + 512] = (v2 - mu) * rstd * gw[tid + 512] + bw[tid + 512];
}

// ---------------- generic SGEMM: C = act(A[M,K]@W[K,N] + bias) (+ res) ----
template<int ACT, bool RES>
__global__ __launch_bounds__(256) void gemm_kernel(
    const float* __restrict__ A, const float* __restrict__ W,
    const float* __restrict__ bias, const float* __restrict__ res,
    float* __restrict__ C, int M, int N, int K)
{
    __shared__ float As[16][64];
    __shared__ float Bs[16][64];
    int t  = threadIdx.x;
    int bm = blockIdx.y << 6;
    int bn = blockIdx.x << 6;
    int ty = t >> 4, tx = t & 15;
    int arow = t >> 2,  acol = (t & 3) << 2;
    int brow = t >> 4,  bcol = (t & 15) << 2;
    const float* Ap = A + (size_t)(bm + arow) * K + acol;
    const float* Wp = W + (size_t)brow * N + bn + bcol;
    float acc[4][4] = {};
    for (int k0 = 0; k0 < K; k0 += 16) {
        float4 av = *reinterpret_cast<const float4*>(Ap + k0);
        As[acol + 0][arow] = av.x;
        As[acol + 1][arow] = av.y;
        As[acol + 2][arow] = av.z;
        As[acol + 3][arow] = av.w;
        *reinterpret_cast<float4*>(&Bs[brow][bcol]) =
            *reinterpret_cast<const float4*>(Wp + (size_t)k0 * N);
        __syncthreads();
        #pragma unroll
        for (int kk = 0; kk < 16; ++kk) {
            float4 a = *reinterpret_cast<const float4*>(&As[kk][ty << 2]);
            float4 b = *reinterpret_cast<const float4*>(&Bs[kk][tx << 2]);
            acc[0][0] = fmaf(a.x, b.x, acc[0][0]);
            acc[0][1] = fmaf(a.x, b.y, acc[0][1]);
            acc[0][2] = fmaf(a.x, b.z, acc[0][2]);
            acc[0][3] = fmaf(a.x, b.w, acc[0][3]);
            acc[1][0] = fmaf(a.y, b.x, acc[1][0]);
            acc[1][1] = fmaf(a.y, b.y, acc[1][1]);
            acc[1][2] = fmaf(a.y, b.z, acc[1][2]);
            acc[1][3] = fmaf(a.y, b.w, acc[1][3]);
            acc[2][0] = fmaf(a.z, b.x, acc[2][0]);
            acc[2][1] = fmaf(a.z, b.y, acc[2][1]);
            acc[2][2] = fmaf(a.z, b.z, acc[2][2]);
            acc[2][3] = fmaf(a.z, b.w, acc[2][3]);
            acc[3][0] = fmaf(a.w, b.x, acc[3][0]);
            acc[3][1] = fmaf(a.w, b.y, acc[3][1]);
            acc[3][2] = fmaf(a.w, b.z, acc[3][2]);
            acc[3][3] = fmaf(a.w, b.w, acc[3][3]);
        }
        __syncthreads();
    }
    #pragma unroll
    for (int i = 0; i < 4; ++i) {
        int row = bm + (ty << 2) + i;
        #pragma unroll
        for (int j = 0; j < 4; ++j) {
            int col = bn + (tx << 2) + j;
            float v = acc[i][j] + bias[col];
            if (ACT == 1) v = v / (1.f + __expf(-v));                      // silu
            if (ACT == 2) v = 0.5f * v * (1.f + erff(v * 0.70710678118654752f)); // gelu exact
            if (RES) v += res[(size_t)row * N + col];
            C[(size_t)row * N + col] = v;
        }
    }
}

// ================== warp-level bf16 MMA (plain PTX, works on sm_103) =====
__device__ __forceinline__ void mma_bf16(float* d, const uint32_t* a,
                                         uint32_t b0, uint32_t b1) {
    asm volatile(
        "mma.sync.aligned.m16n8k16.row.col.f32.bf16.bf16.f32 "
        "{%0,%1,%2,%3}, {%4,%5,%6,%7}, {%8,%9}, {%0,%1,%2,%3};"
        : "+f"(d[0]), "+f"(d[1]), "+f"(d[2]), "+f"(d[3])
        : "r"(a[0]), "r"(a[1]), "r"(a[2]), "r"(a[3]), "r"(b0), "r"(b1));
}

// pack two floats' bf16-hi parts and bf16-lo residuals into uint32s
__device__ __forceinline__ void split2(float x0, float x1, uint32_t& hw, uint32_t& lw) {
    __nv_bfloat16 h0 = __float2bfloat16(x0);
    __nv_bfloat16 h1 = __float2bfloat16(x1);
    float r0 = x0 - __bfloat162float(h0);
    float r1 = x1 - __bfloat162float(h1);
    __nv_bfloat162 hp; hp.x = h0; hp.y = h1;
    __nv_bfloat162 lp = __floats2bfloat162_rn(r0, r1);
    hw = *reinterpret_cast<uint32_t*>(&hp);
    lw = *reinterpret_cast<uint32_t*>(&lp);
}

// ---------------- tensor-core distance-bias MLP ----------------
// bias[b,i,j,h] = silu(dist[b,i,j,:] @ W1 + b1) @ W2 + b2, stored [b][h][i][j]
// One CTA per (b,i): 256 threads = 8 warps, TWO 16-row m-tiles per warp.
// Stride-36 W1 staging: b-frag banks (4g + tig) mod 32, conflict-free.
// Split-bf16 3-term MMA with INDEPENDENT accumulator chains per term:
// 3 chains of 4 MMAs per m-tile (6 chains/warp in flight) instead of one
// serial chain of 12 — measured issue was 32.8% latency-bound on the RAW
// chain at 2 warps/SMSP.
#define W1S 36
__global__ __launch_bounds__(256) void rbias_mma_kernel(
    const float* __restrict__ dist, const float* __restrict__ W1,
    const float* __restrict__ b1,   const float* __restrict__ W2,
    const float* __restrict__ b2,   float* __restrict__ biasT)
{
    __shared__ uint32_t sBhi[64 * W1S];
    __shared__ uint32_t sBlo[64 * W1S];
    __shared__ float    sW2[768];
    __shared__ float    sB1[64];
    __shared__ float    sOut[256 * 13];

    int bi   = blockIdx.x;               // b*256 + i
    int bb   = bi >> 8, ii = bi & 255;
    int tid  = threadIdx.x;
    int warp = tid >> 5, lane = tid & 31;
    int g    = lane >> 2, tig = lane & 3;

    // ---- A fragments (2 m-tiles, held for all 12 chunks) ----
    uint32_t ahi[2][16], alo[2][16];
    #pragma unroll
    for (int mt = 0; mt < 2; ++mt) {
        const float* dp0 = dist + ((size_t)(bi << 8) + warp * 32 + mt * 16 + g) * DDIM;
        const float* dp1 = dp0 + 8 * DDIM;
        #pragma unroll
        for (int kt = 0; kt < 4; ++kt) {
            int k0 = kt * 16 + tig * 2;
            float2 v;
            v = *reinterpret_cast<const float2*>(dp0 + k0);
            split2(v.x, v.y, ahi[mt][kt * 4 + 0], alo[mt][kt * 4 + 0]);
            v = *reinterpret_cast<const float2*>(dp1 + k0);
            split2(v.x, v.y, ahi[mt][kt * 4 + 1], alo[mt][kt * 4 + 1]);
            v = *reinterpret_cast<const float2*>(dp0 + k0 + 8);
            split2(v.x, v.y, ahi[mt][kt * 4 + 2], alo[mt][kt * 4 + 2]);
            v = *reinterpret_cast<const float2*>(dp1 + k0 + 8);
            split2(v.x, v.y, ahi[mt][kt * 4 + 3], alo[mt][kt * 4 + 3]);
        }
    }

    // acc[mt*2 + rowhalf][o]: rowhalf 0 -> row g, 1 -> row g+8
    float acc[4][12] = {};

    #pragma unroll 1
    for (int cc = 0; cc < 12; ++cc) {
        __syncthreads();   // previous chunk fully consumed
        // stage W1 chunk split-bf16: [c][kp] stride-36 words
        for (int idx = tid; idx < 2048; idx += 256) {
            int c = idx & 63, kp = idx >> 6;          // kp = k/2, 0..31
            const float* wp = W1 + (size_t)(kp * 2) * DMODEL + (cc << 6) + c;
            uint32_t hw, lw;
            split2(wp[0], wp[DMODEL], hw, lw);
            sBhi[c * W1S + kp] = hw;
            sBlo[c * W1S + kp] = lw;
        }
        for (int idx = tid; idx < 768; idx += 256)
            sW2[idx] = W2[(size_t)cc * 768 + idx];
        if (tid < 64) sB1[tid] = b1[(cc << 6) + tid];
        __syncthreads();

        #pragma unroll 1
        for (int nt = 0; nt < 8; ++nt) {
            int nb = (nt * 8 + g) * W1S;
            uint32_t bh[8], bl[8];
            #pragma unroll
            for (int kt = 0; kt < 4; ++kt) {
                bh[kt * 2]     = sBhi[nb + kt * 8 + tig];
                bh[kt * 2 + 1] = sBhi[nb + kt * 8 + 4 + tig];
                bl[kt * 2]     = sBlo[nb + kt * 8 + tig];
                bl[kt * 2 + 1] = sBlo[nb + kt * 8 + 4 + tig];
            }
            // epilogue constants for this n-tile (shared by both m-tiles)
            int c0 = nt * 8 + (tig << 1);
            float bias0 = sB1[c0], bias1 = sB1[c0 + 1];
            const float4* w2a = reinterpret_cast<const float4*>(sW2 + c0 * 12);
            const float4* w2b = reinterpret_cast<const float4*>(sW2 + (c0 + 1) * 12);
            float4 wa0 = w2a[0], wa1 = w2a[1], wa2 = w2a[2];
            float4 wb0 = w2b[0], wb1 = w2b[1], wb2 = w2b[2];

            // 6 independent MMA chains (3 split-terms x 2 m-tiles),
            // interleaved issue order for maximum pipelined overlap
            float dh[2][4] = {}, dl[2][4] = {}, dr[2][4] = {};
            #pragma unroll
            for (int kt = 0; kt < 4; ++kt) {
                mma_bf16(dh[0], &ahi[0][kt * 4], bh[kt * 2], bh[kt * 2 + 1]);
                mma_bf16(dh[1], &ahi[1][kt * 4], bh[kt * 2], bh[kt * 2 + 1]);
                mma_bf16(dl[0], &ahi[0][kt * 4], bl[kt * 2], bl[kt * 2 + 1]);
                mma_bf16(dl[1], &ahi[1][kt * 4], bl[kt * 2], bl[kt * 2 + 1]);
                mma_bf16(dr[0], &alo[0][kt * 4], bh[kt * 2], bh[kt * 2 + 1]);
                mma_bf16(dr[1], &alo[1][kt * 4], bh[kt * 2], bh[kt * 2 + 1]);
            }

            #pragma unroll
            for (int mt = 0; mt < 2; ++mt) {
                // D frag: d0:(g,c0) d1:(g,c0+1) d2:(g+8,c0) d3:(g+8,c0+1)
                float h0 = dh[mt][0] + dl[mt][0] + dr[mt][0] + bias0;
                float h1 = dh[mt][1] + dl[mt][1] + dr[mt][1] + bias1;
                float h2 = dh[mt][2] + dl[mt][2] + dr[mt][2] + bias0;
                float h3 = dh[mt][3] + dl[mt][3] + dr[mt][3] + bias1;
                float s0 = h0 / (1.f + __expf(-h0));
                float s1 = h1 / (1.f + __expf(-h1));
                float s2 = h2 / (1.f + __expf(-h2));
                float s3 = h3 / (1.f + __expf(-h3));
                float* A0 = acc[mt * 2];
                float* A1 = acc[mt * 2 + 1];
                A0[0]  = fmaf(s0, wa0.x, fmaf(s1, wb0.x, A0[0]));
                A1[0]  = fmaf(s2, wa0.x, fmaf(s3, wb0.x, A1[0]));
                A0[1]  = fmaf(s0, wa0.y, fmaf(s1, wb0.y, A0[1]));
                A1[1]  = fmaf(s2, wa0.y, fmaf(s3, wb0.y, A1[1]));
                A0[2]  = fmaf(s0, wa0.z, fmaf(s1, wb0.z, A0[2]));
                A1[2]  = fmaf(s2, wa0.z, fmaf(s3, wb0.z, A1[2]));
                A0[3]  = fmaf(s0, wa0.w, fmaf(s1, wb0.w, A0[3]));
                A1[3]  = fmaf(s2, wa0.w, fmaf(s3, wb0.w, A1[3]));
                A0[4]  = fmaf(s0, wa1.x, fmaf(s1, wb1.x, A0[4]));
                A1[4]  = fmaf(s2, wa1.x, fmaf(s3, wb1.x, A1[4]));
                A0[5]  = fmaf(s0, wa1.y, fmaf(s1, wb1.y, A0[5]));
                A1[5]  = fmaf(s2, wa1.y, fmaf(s3, wb1.y, A1[5]));
                A0[6]  = fmaf(s0, wa1.z, fmaf(s1, wb1.z, A0[6]));
                A1[6]  = fmaf(s2, wa1.z, fmaf(s3, wb1.z, A1[6]));
                A0[7]  = fmaf(s0, wa1.w, fmaf(s1, wb1.w, A0[7]));
                A1[7]  = fmaf(s2, wa1.w, fmaf(s3, wb1.w, A1[7]));
                A0[8]  = fmaf(s0, wa2.x, fmaf(s1, wb2.x, A0[8]));
                A1[8]  = fmaf(s2, wa2.x, fmaf(s3, wb2.x, A1[8]));
                A0[9]  = fmaf(s0, wa2.y, fmaf(s1, wb2.y, A0[9]));
                A1[9]  = fmaf(s2, wa2.y, fmaf(s3, wb2.y, A1[9]));
                A0[10] = fmaf(s0, wa2.z, fmaf(s1, wb2.z, A0[10]));
                A1[10] = fmaf(s2, wa2.z, fmaf(s3, wb2.z, A1[10]));
                A0[11] = fmaf(s0, wa2.w, fmaf(s1, wb2.w, A0[11]));
                A1[11] = fmaf(s2, wa2.w, fmaf(s3, wb2.w, A1[11]));
            }
        }
    }

    // ---- quad reduction (lanes tig=0..3 hold disjoint c-subsets) ----
    #pragma unroll
    for (int v = 0; v < 4; ++v) {
        #pragma unroll
        for (int o = 0; o < 12; ++o) {
            acc[v][o] += __shfl_xor_sync(0xffffffffu, acc[v][o], 1);
            acc[v][o] += __shfl_xor_sync(0xffffffffu, acc[v][o], 2);
        }
    }
    __syncthreads();
    if (tig == 0) {
        #pragma unroll
        for (int mt = 0; mt < 2; ++mt) {
            int r0 = warp * 32 + mt * 16 + g;
            #pragma unroll
            for (int o = 0; o < 12; ++o) {
                sOut[r0 * 13 + o]       = acc[mt * 2][o];
                sOut[(r0 + 8) * 13 + o] = acc[mt * 2 + 1][o];
            }
        }
    }
    __syncthreads();

    // coalesced store: biasT[bb][o][ii][j]
    for (int idx = tid; idx < 256 * 12; idx += 256) {
        int o = idx >> 8, j = idx & 255;
        size_t base = (((size_t)bb * NHEAD + o) * NSEQ + ii) * NSEQ;
        biasT[base + j] = sOut[j * 13 + o] + b2[o];
    }
}

// ---------------- attention: one block per (b,h,i) query row -------------
__global__ __launch_bounds__(128) void attn_kernel(
    const float* __restrict__ qkv, const float* __restrict__ biasT,
    const int* __restrict__ mask, float* __restrict__ ctx)
{
    int i = blockIdx.x, h = blockIdx.y, b = blockIdx.z;
    int tid = threadIdx.x;
    __shared__ float qs[64];
    __shared__ float ps[256];
    __shared__ float red[4];
    __shared__ float part[2][64];

    size_t qoff = ((size_t)(b * NSEQ + i)) * 2304 + (size_t)h * HDIM;
    if (tid < 64) qs[tid] = qkv[qoff + tid];
    __syncthreads();

    float lv[2];
    #pragma unroll
    for (int u = 0; u < 2; ++u) {
        int j = tid + (u << 7);
        const float* kp = qkv + ((size_t)(b * NSEQ + j)) * 2304 + DMODEL + h * HDIM;
        float a0 = 0.f, a1 = 0.f;
        #pragma unroll
        for (int d = 0; d < 64; d += 4) {
            float4 kv4 = *reinterpret_cast<const float4*>(kp + d);
            a0 = fmaf(qs[d],     kv4.x, a0);
            a1 = fmaf(qs[d + 1], kv4.y, a1);
            a0 = fmaf(qs[d + 2], kv4.z, a0);
            a1 = fmaf(qs[d + 3], kv4.w, a1);
        }
        float lg = (a0 + a1) * 0.125f
                 + biasT[(((size_t)b * NHEAD + h) * NSEQ + i) * NSEQ + j];
        if (mask[((size_t)(b * NSEQ + i)) * NSEQ + j] == 0) lg = -1e30f;
        lv[u] = lg;
    }

    int wid = tid >> 5, lane = tid & 31;
    float m = warp_max(fmaxf(lv[0], lv[1]));
    if (!lane) red[wid] = m;
    __syncthreads();
    m = fmaxf(fmaxf(red[0], red[1]), fmaxf(red[2], red[3]));
    __syncthreads();                     // red reuse below

    float e0 = __expf(lv[0] - m), e1 = __expf(lv[1] - m);
    ps[tid] = e0; ps[tid + 128] = e1;
    float s = warp_sum(e0 + e1);
    if (!lane) red[wid] = s;
    __syncthreads();
    float inv = 1.f / (red[0] + red[1] + red[2] + red[3]);

    int d = tid & 63, pr = tid >> 6;
    const float* vp = qkv + 2 * DMODEL + (size_t)h * HDIM + d;
    float a0 = 0.f, a1 = 0.f;
    int j0 = pr << 7;
    #pragma unroll 4
    for (int j = j0; j < j0 + 128; j += 2) {
        a0 = fmaf(ps[j],     vp[((size_t)(b * NSEQ + j)) * 2304],     a0);
        a1 = fmaf(ps[j + 1], vp[((size_t)(b * NSEQ + j + 1)) * 2304], a1);
    }
    part[pr][d] = a0 + a1;
    __syncthreads();
    if (tid < 64)
        ctx[((size_t)(b * NSEQ + i)) * DMODEL + h * HDIM + tid] =
            (part[0][tid] + part[1][tid]) * inv;
}

// ---------------- a = ctx * sigmoid(gated) ----------------
__global__ __launch_bounds__(256) void gate_mul_kernel(
    const float* __restrict__ ctx, const float* __restrict__ gated,
    float* __restrict__ a, int n)
{
    int idx = blockIdx.x * 256 + threadIdx.x;
    if (idx < n) {
        float g = gated[idx];
        a[idx] = ctx[idx] * (1.f / (1.f + __expf(-g)));
    }
}

// ---------------- launch ----------------
extern "C" void kernel_launch(void* const* d_in, const int* in_sizes, int n_in,
                              void* d_out, int out_size)
{
    const float* x       = (const float*)d_in[0];
    const float* dist    = (const float*)d_in[1];
    const int*   mask    = (const int*)  d_in[2];
    const float* qkv_w   = (const float*)d_in[3];
    const float* qkv_b   = (const float*)d_in[4];
    const float* out_w   = (const float*)d_in[5];
    const float* out_b   = (const float*)d_in[6];
    const float* rb_w1   = (const float*)d_in[7];
    const float* rb_b1   = (const float*)d_in[8];
    const float* rb_w2   = (const float*)d_in[9];
    const float* rb_b2   = (const float*)d_in[10];
    const float* gate_w1 = (const float*)d_in[11];
    const float* gate_b1 = (const float*)d_in[12];
    const float* gate_w2 = (const float*)d_in[13];
    const float* gate_b2 = (const float*)d_in[14];
    const float* ff_w1   = (const float*)d_in[15];
    const float* ff_b1   = (const float*)d_in[16];
    const float* ff_w2   = (const float*)d_in[17];
    const float* ff_b2   = (const float*)d_in[18];
    const float* ln1_g   = (const float*)d_in[19];
    const float* ln1_b   = (const float*)d_in[20];
    const float* ln2_g   = (const float*)d_in[21];
    const float* ln2_b   = (const float*)d_in[22];
    float* out = (float*)d_out;

    float *xn, *qkv, *s1, *gated, *biasT, *ctx, *a, *x2, *y, *ffh;
    cudaGetSymbolAddress((void**)&xn,    g_xn);
    cudaGetSymbolAddress((void**)&qkv,   g_qkv);
    cudaGetSymbolAddress((void**)&s1,    g_s1);
    cudaGetSymbolAddress((void**)&gated, g_gated);
    cudaGetSymbolAddress((void**)&biasT, g_biasT);
    cudaGetSymbolAddress((void**)&ctx,   g_ctx);
    cudaGetSymbolAddress((void**)&a,     g_a);
    cudaGetSymbolAddress((void**)&x2,    g_x2);
    cudaGetSymbolAddress((void**)&y,     g_y);
    cudaGetSymbolAddress((void**)&ffh,   g_ffh);

    // LN1
    ln_kernel<<<MROWS, 256>>>(x, ln1_g, ln1_b, xn);
    // qkv = xn @ qkv_w + b
    gemm_kernel<0, false><<<dim3(36, 16), 256>>>(xn, qkv_w, qkv_b, nullptr, qkv,
                                                 MROWS, 3 * DMODEL, DMODEL);
    // s1 = silu(xn @ gate_w1 + b)
    gemm_kernel<1, false><<<dim3(12, 16), 256>>>(xn, gate_w1, gate_b1, nullptr, s1,
                                                 MROWS, DMODEL, DMODEL);
    // fused distance-bias MLP (warp-level bf16 tensor cores, 8 warps x 2 m-tiles)
    rbias_mma_kernel<<<MROWS, 256>>>(dist, rb_w1, rb_b1, rb_w2, rb_b2, biasT);
    // attention
    attn_kernel<<<dim3(NSEQ, NHEAD, 4), 128>>>(qkv, biasT, mask, ctx);
    // gated = s1 @ gate_w2 + b
    gemm_kernel<0, false><<<dim3(12, 16), 256>>>(s1, gate_w2, gate_b2, nullptr, gated,
                                                 MROWS, DMODEL, DMODEL);
    // a = ctx * sigmoid(gated)
    gate_mul_kernel<<<(MROWS * DMODEL + 255) / 256, 256>>>(ctx, gated, a, MROWS * DMODEL);
    // x2 = x + a @ out_w + out_b
    gemm_kernel<0, true><<<dim3(12, 16), 256>>>(a, out_w, out_b, x, x2,
                                                MROWS, DMODEL, DMODEL);
    // LN2
    ln_kernel<<<MROWS, 256>>>(x2, ln2_g, ln2_b, y);
    // ffh = gelu(y @ ff_w1 + b)
    gemm_kernel<2, false><<<dim3(24, 16), 256>>>(y, ff_w1, ff_b1, nullptr, ffh,
                                                 MROWS, 2 * DMODEL, DMODEL);
    // out = x2 + ffh @ ff_w2 + b
    gemm_kernel<0, true><<<dim3(12, 16), 256>>>(ffh, ff_w2, ff_b2, x2, out,
                                                MROWS, DMODEL, 2 * DMODEL);
}

// round 17
// speedup vs baseline: 1.4984x; 1.4984x over previous
#include <cuda_runtime.h>
#include <cuda_bf16.h>
#include <math.h>
#include <stdint.h>

// Shapes (fixed by the problem)
// B=4, N=256, D=768, H=12, DD=64, HD=64, M = B*N = 1024
#define MROWS 1024
#define DMODEL 768
#define NSEQ 256
#define NHEAD 12
#define HDIM 64
#define DDIM 64

// ---------------- scratch (no allocations allowed) ----------------
__device__ float g_xn   [MROWS * DMODEL];
__device__ float g_qkv  [MROWS * 3 * DMODEL];
__device__ float g_s1   [MROWS * DMODEL];     // silu(xn@gate_w1+b1)
__device__ float g_gated[MROWS * DMODEL];
__device__ float g_biasT[4 * NHEAD * NSEQ * NSEQ];  // [b][h][i][j]
__device__ float g_ctx  [MROWS * DMODEL];
__device__ float g_a    [MROWS * DMODEL];     // ctx * sigmoid(gated)
__device__ float g_x2   [MROWS * DMODEL];
__device__ float g_y    [MROWS * DMODEL];
__device__ float g_ffh  [MROWS * 2 * DMODEL];

// ---------------- helpers ----------------
__device__ __forceinline__ float warp_sum(float v) {
    #pragma unroll
    for (int o = 16; o > 0; o >>= 1) v += __shfl_xor_sync(0xffffffffu, v, o);
    return v;
}
__device__ __forceinline__ float warp_max(float v) {
    #pragma unroll
    for (int o = 16; o > 0; o >>= 1) v = fmaxf(v, __shfl_xor_sync(0xffffffffu, v, o));
    return v;
}

// ---------------- LayerNorm: one block per row of 768 ----------------
__global__ __launch_bounds__(256) void ln_kernel(
    const float* __restrict__ x, const float* __restrict__ gw,
    const float* __restrict__ bw, float* __restrict__ out)
{
    int row = blockIdx.x;
    int tid = threadIdx.x;
    const float* xr = x + (size_t)row * DMODEL;
    float v0 = xr[tid], v1 = xr[tid + 256], v2 = xr[tid + 512];
    float s  = v0 + v1 + v2;
    float s2 = v0 * v0 + v1 * v1 + v2 * v2;
    __shared__ float sm[8], sm2[8], stat[2];
    float ws = warp_sum(s), ws2 = warp_sum(s2);
    int wid = tid >> 5, lane = tid & 31;
    if (!lane) { sm[wid] = ws; sm2[wid] = ws2; }
    __syncthreads();
    if (tid == 0) {
        float S = 0.f, S2 = 0.f;
        #pragma unroll
        for (int i = 0; i < 8; ++i) { S += sm[i]; S2 += sm2[i]; }
        float mu  = S * (1.f / DMODEL);
        float var = S2 * (1.f / DMODEL) - mu * mu;
        stat[0] = mu;
        stat[1] = rsqrtf(var + 1e-5f);
    }
    __syncthreads();
    float mu = stat[0], rstd = stat[1];
    float* orow = out + (size_t)row * DMODEL;
    orow[tid]       = (v0 - mu) * rstd * gw[tid]       + bw[tid];
    orow[tid + 256] = (v1 - mu) * rstd * gw[tid + 256] + bw[tid + 256];
    orow[tid + 512] = (v2 - mu) * rstd * gw[tid + 512] + bw[tid + 512];
}

// ---------------- generic SGEMM: C = act(A[M,K]@W[K,N] + bias) (+ res) ----
template<int ACT, bool RES>
__global__ __launch_bounds__(256) void gemm_kernel(
    const float* __restrict__ A, const float* __restrict__ W,
    const float* __restrict__ bias, const float* __restrict__ res,
    float* __restrict__ C, int M, int N, int K)
{
    __shared__ float As[16][64];
    __shared__ float Bs[16][64];
    int t  = threadIdx.x;
    int bm = blockIdx.y << 6;
    int bn = blockIdx.x << 6;
    int ty = t >> 4, tx = t & 15;
    int arow = t >> 2,  acol = (t & 3) << 2;
    int brow = t >> 4,  bcol = (t & 15) << 2;
    const float* Ap = A + (size_t)(bm + arow) * K + acol;
    const float* Wp = W + (size_t)brow * N + bn + bcol;
    float acc[4][4] = {};
    for (int k0 = 0; k0 < K; k0 += 16) {
        float4 av = *reinterpret_cast<const float4*>(Ap + k0);
        As[acol + 0][arow] = av.x;
        As[acol + 1][arow] = av.y;
        As[acol + 2][arow] = av.z;
        As[acol + 3][arow] = av.w;
        *reinterpret_cast<float4*>(&Bs[brow][bcol]) =
            *reinterpret_cast<const float4*>(Wp + (size_t)k0 * N);
        __syncthreads();
        #pragma unroll
        for (int kk = 0; kk < 16; ++kk) {
            float4 a = *reinterpret_cast<const float4*>(&As[kk][ty << 2]);
            float4 b = *reinterpret_cast<const float4*>(&Bs[kk][tx << 2]);
            acc[0][0] = fmaf(a.x, b.x, acc[0][0]);
            acc[0][1] = fmaf(a.x, b.y, acc[0][1]);
            acc[0][2] = fmaf(a.x, b.z, acc[0][2]);
            acc[0][3] = fmaf(a.x, b.w, acc[0][3]);
            acc[1][0] = fmaf(a.y, b.x, acc[1][0]);
            acc[1][1] = fmaf(a.y, b.y, acc[1][1]);
            acc[1][2] = fmaf(a.y, b.z, acc[1][2]);
            acc[1][3] = fmaf(a.y, b.w, acc[1][3]);
            acc[2][0] = fmaf(a.z, b.x, acc[2][0]);
            acc[2][1] = fmaf(a.z, b.y, acc[2][1]);
            acc[2][2] = fmaf(a.z, b.z, acc[2][2]);
            acc[2][3] = fmaf(a.z, b.w, acc[2][3]);
            acc[3][0] = fmaf(a.w, b.x, acc[3][0]);
            acc[3][1] = fmaf(a.w, b.y, acc[3][1]);
            acc[3][2] = fmaf(a.w, b.z, acc[3][2]);
            acc[3][3] = fmaf(a.w, b.w, acc[3][3]);
        }
        __syncthreads();
    }
    #pragma unroll
    for (int i = 0; i < 4; ++i) {
        int row = bm + (ty << 2) + i;
        #pragma unroll
        for (int j = 0; j < 4; ++j) {
            int col = bn + (tx << 2) + j;
            float v = acc[i][j] + bias[col];
            if (ACT == 1) v = v / (1.f + __expf(-v));                      // silu
            if (ACT == 2) v = 0.5f * v * (1.f + erff(v * 0.70710678118654752f)); // gelu exact
            if (RES) v += res[(size_t)row * N + col];
            C[(size_t)row * N + col] = v;
        }
    }
}

// ================== warp-level bf16 MMA (plain PTX, works on sm_103) =====
__device__ __forceinline__ void mma_bf16(float* d, const uint32_t* a,
                                         uint32_t b0, uint32_t b1) {
    asm volatile(
        "mma.sync.aligned.m16n8k16.row.col.f32.bf16.bf16.f32 "
        "{%0,%1,%2,%3}, {%4,%5,%6,%7}, {%8,%9}, {%0,%1,%2,%3};"
        : "+f"(d[0]), "+f"(d[1]), "+f"(d[2]), "+f"(d[3])
        : "r"(a[0]), "r"(a[1]), "r"(a[2]), "r"(a[3]), "r"(b0), "r"(b1));
}

// pack two floats' bf16-hi parts and bf16-lo residuals into uint32s
__device__ __forceinline__ void split2(float x0, float x1, uint32_t& hw, uint32_t& lw) {
    __nv_bfloat16 h0 = __float2bfloat16(x0);
    __nv_bfloat16 h1 = __float2bfloat16(x1);
    float r0 = x0 - __bfloat162float(h0);
    float r1 = x1 - __bfloat162float(h1);
    __nv_bfloat162 hp; hp.x = h0; hp.y = h1;
    __nv_bfloat162 lp = __floats2bfloat162_rn(r0, r1);
    hw = *reinterpret_cast<uint32_t*>(&hp);
    lw = *reinterpret_cast<uint32_t*>(&lp);
}

// ---------------- tensor-core distance-bias MLP (round-14 proven form) ----
// bias[b,i,j,h] = silu(dist[b,i,j,:] @ W1 + b1) @ W2 + b2, stored [b][h][i][j]
// One CTA per (b,i): 256 threads = 8 warps, TWO 16-row m-tiles per warp.
// Stride-36 W1 staging: b-frag banks (4g + tig) mod 32, conflict-free.
// Split-bf16 3-term MMA: D = Ahi@Bhi + Ahi@Blo + Alo@Bhi (rel-err ~6e-7 e2e).
#define W1S 36
__global__ __launch_bounds__(256) void rbias_mma_kernel(
    const float* __restrict__ dist, const float* __restrict__ W1,
    const float* __restrict__ b1,   const float* __restrict__ W2,
    const float* __restrict__ b2,   float* __restrict__ biasT)
{
    __shared__ uint32_t sBhi[64 * W1S];
    __shared__ uint32_t sBlo[64 * W1S];
    __shared__ float    sW2[768];
    __shared__ float    sB1[64];
    __shared__ float    sOut[256 * 13];

    int bi   = blockIdx.x;               // b*256 + i
    int bb   = bi >> 8, ii = bi & 255;
    int tid  = threadIdx.x;
    int warp = tid >> 5, lane = tid & 31;
    int g    = lane >> 2, tig = lane & 3;

    // ---- A fragments (2 m-tiles, held for all 12 chunks) ----
    uint32_t ahi[2][16], alo[2][16];
    #pragma unroll
    for (int mt = 0; mt < 2; ++mt) {
        const float* dp0 = dist + ((size_t)(bi << 8) + warp * 32 + mt * 16 + g) * DDIM;
        const float* dp1 = dp0 + 8 * DDIM;
        #pragma unroll
        for (int kt = 0; kt < 4; ++kt) {
            int k0 = kt * 16 + tig * 2;
            float2 v;
            v = *reinterpret_cast<const float2*>(dp0 + k0);
            split2(v.x, v.y, ahi[mt][kt * 4 + 0], alo[mt][kt * 4 + 0]);
            v = *reinterpret_cast<const float2*>(dp1 + k0);
            split2(v.x, v.y, ahi[mt][kt * 4 + 1], alo[mt][kt * 4 + 1]);
            v = *reinterpret_cast<const float2*>(dp0 + k0 + 8);
            split2(v.x, v.y, ahi[mt][kt * 4 + 2], alo[mt][kt * 4 + 2]);
            v = *reinterpret_cast<const float2*>(dp1 + k0 + 8);
            split2(v.x, v.y, ahi[mt][kt * 4 + 3], alo[mt][kt * 4 + 3]);
        }
    }

    // acc[mt*2 + rowhalf][o]: rowhalf 0 -> row g, 1 -> row g+8
    float acc[4][12] = {};

    #pragma unroll 1
    for (int cc = 0; cc < 12; ++cc) {
        __syncthreads();   // previous chunk fully consumed
        // stage W1 chunk split-bf16: [c][kp] stride-36 words
        for (int idx = tid; idx < 2048; idx += 256) {
            int c = idx & 63, kp = idx >> 6;          // kp = k/2, 0..31
            const float* wp = W1 + (size_t)(kp * 2) * DMODEL + (cc << 6) + c;
            uint32_t hw, lw;
            split2(wp[0], wp[DMODEL], hw, lw);
            sBhi[c * W1S + kp] = hw;
            sBlo[c * W1S + kp] = lw;
        }
        for (int idx = tid; idx < 768; idx += 256)
            sW2[idx] = W2[(size_t)cc * 768 + idx];
        if (tid < 64) sB1[tid] = b1[(cc << 6) + tid];
        __syncthreads();

        #pragma unroll 1
        for (int nt = 0; nt < 8; ++nt) {
            int nb = (nt * 8 + g) * W1S;
            uint32_t bh[8], bl[8];
            #pragma unroll
            for (int kt = 0; kt < 4; ++kt) {
                bh[kt * 2]     = sBhi[nb + kt * 8 + tig];
                bh[kt * 2 + 1] = sBhi[nb + kt * 8 + 4 + tig];
                bl[kt * 2]     = sBlo[nb + kt * 8 + tig];
                bl[kt * 2 + 1] = sBlo[nb + kt * 8 + 4 + tig];
            }
            // epilogue constants for this n-tile (shared by both m-tiles)
            int c0 = nt * 8 + (tig << 1);
            float bias0 = sB1[c0], bias1 = sB1[c0 + 1];
            const float4* w2a = reinterpret_cast<const float4*>(sW2 + c0 * 12);
            const float4* w2b = reinterpret_cast<const float4*>(sW2 + (c0 + 1) * 12);
            float4 wa0 = w2a[0], wa1 = w2a[1], wa2 = w2a[2];
            float4 wb0 = w2b[0], wb1 = w2b[1], wb2 = w2b[2];

            #pragma unroll
            for (int mt = 0; mt < 2; ++mt) {
                float d[4] = {0.f, 0.f, 0.f, 0.f};
                #pragma unroll
                for (int kt = 0; kt < 4; ++kt)
                    mma_bf16(d, &ahi[mt][kt * 4], bh[kt * 2], bh[kt * 2 + 1]);
                #pragma unroll
                for (int kt = 0; kt < 4; ++kt)
                    mma_bf16(d, &ahi[mt][kt * 4], bl[kt * 2], bl[kt * 2 + 1]);
                #pragma unroll
                for (int kt = 0; kt < 4; ++kt)
                    mma_bf16(d, &alo[mt][kt * 4], bh[kt * 2], bh[kt * 2 + 1]);

                // D frag: d0:(g,c0) d1:(g,c0+1) d2:(g+8,c0) d3:(g+8,c0+1)
                float h0 = d[0] + bias0, h1 = d[1] + bias1;
                float h2 = d[2] + bias0, h3 = d[3] + bias1;
                float s0 = h0 / (1.f + __expf(-h0));
                float s1 = h1 / (1.f + __expf(-h1));
                float s2 = h2 / (1.f + __expf(-h2));
                float s3 = h3 / (1.f + __expf(-h3));
                float* A0 = acc[mt * 2];
                float* A1 = acc[mt * 2 + 1];
                A0[0]  = fmaf(s0, wa0.x, fmaf(s1, wb0.x, A0[0]));
                A1[0]  = fmaf(s2, wa0.x, fmaf(s3, wb0.x, A1[0]));
                A0[1]  = fmaf(s0, wa0.y, fmaf(s1, wb0.y, A0[1]));
                A1[1]  = fmaf(s2, wa0.y, fmaf(s3, wb0.y, A1[1]));
                A0[2]  = fmaf(s0, wa0.z, fmaf(s1, wb0.z, A0[2]));
                A1[2]  = fmaf(s2, wa0.z, fmaf(s3, wb0.z, A1[2]));
                A0[3]  = fmaf(s0, wa0.w, fmaf(s1, wb0.w, A0[3]));
                A1[3]  = fmaf(s2, wa0.w, fmaf(s3, wb0.w, A1[3]));
                A0[4]  = fmaf(s0, wa1.x, fmaf(s1, wb1.x, A0[4]));
                A1[4]  = fmaf(s2, wa1.x, fmaf(s3, wb1.x, A1[4]));
                A0[5]  = fmaf(s0, wa1.y, fmaf(s1, wb1.y, A0[5]));
                A1[5]  = fmaf(s2, wa1.y, fmaf(s3, wb1.y, A1[5]));
                A0[6]  = fmaf(s0, wa1.z, fmaf(s1, wb1.z, A0[6]));
                A1[6]  = fmaf(s2, wa1.z, fmaf(s3, wb1.z, A1[6]));
                A0[7]  = fmaf(s0, wa1.w, fmaf(s1, wb1.w, A0[7]));
                A1[7]  = fmaf(s2, wa1.w, fmaf(s3, wb1.w, A1[7]));
                A0[8]  = fmaf(s0, wa2.x, fmaf(s1, wb2.x, A0[8]));
                A1[8]  = fmaf(s2, wa2.x, fmaf(s3, wb2.x, A1[8]));
                A0[9]  = fmaf(s0, wa2.y, fmaf(s1, wb2.y, A0[9]));
                A1[9]  = fmaf(s2, wa2.y, fmaf(s3, wb2.y, A1[9]));
                A0[10] = fmaf(s0, wa2.z, fmaf(s1, wb2.z, A0[10]));
                A1[10] = fmaf(s2, wa2.z, fmaf(s3, wb2.z, A1[10]));
                A0[11] = fmaf(s0, wa2.w, fmaf(s1, wb2.w, A0[11]));
                A1[11] = fmaf(s2, wa2.w, fmaf(s3, wb2.w, A1[11]));
            }
        }
    }

    // ---- quad reduction (lanes tig=0..3 hold disjoint c-subsets) ----
    #pragma unroll
    for (int v = 0; v < 4; ++v) {
        #pragma unroll
        for (int o = 0; o < 12; ++o) {
            acc[v][o] += __shfl_xor_sync(0xffffffffu, acc[v][o], 1);
            acc[v][o] += __shfl_xor_sync(0xffffffffu, acc[v][o], 2);
        }
    }
    __syncthreads();
    if (tig == 0) {
        #pragma unroll
        for (int mt = 0; mt < 2; ++mt) {
            int r0 = warp * 32 + mt * 16 + g;
            #pragma unroll
            for (int o = 0; o < 12; ++o) {
                sOut[r0 * 13 + o]       = acc[mt * 2][o];
                sOut[(r0 + 8) * 13 + o] = acc[mt * 2 + 1][o];
            }
        }
    }
    __syncthreads();

    // coalesced store: biasT[bb][o][ii][j]
    for (int idx = tid; idx < 256 * 12; idx += 256) {
        int o = idx >> 8, j = idx & 255;
        size_t base = (((size_t)bb * NHEAD + o) * NSEQ + ii) * NSEQ;
        biasT[base + j] = sOut[j * 13 + o] + b2[o];
    }
}

// ---------------- attention: one block per (b,h,i) query row -------------
__global__ __launch_bounds__(128) void attn_kernel(
    const float* __restrict__ qkv, const float* __restrict__ biasT,
    const int* __restrict__ mask, float* __restrict__ ctx)
{
    int i = blockIdx.x, h = blockIdx.y, b = blockIdx.z;
    int tid = threadIdx.x;
    __shared__ float qs[64];
    __shared__ float ps[256];
    __shared__ float red[4];
    __shared__ float part[2][64];

    size_t qoff = ((size_t)(b * NSEQ + i)) * 2304 + (size_t)h * HDIM;
    if (tid < 64) qs[tid] = qkv[qoff + tid];
    __syncthreads();

    float lv[2];
    #pragma unroll
    for (int u = 0; u < 2; ++u) {
        int j = tid + (u << 7);
        const float* kp = qkv + ((size_t)(b * NSEQ + j)) * 2304 + DMODEL + h * HDIM;
        float a0 = 0.f, a1 = 0.f;
        #pragma unroll
        for (int d = 0; d < 64; d += 4) {
            float4 kv4 = *reinterpret_cast<const float4*>(kp + d);
            a0 = fmaf(qs[d],     kv4.x, a0);
            a1 = fmaf(qs[d + 1], kv4.y, a1);
            a0 = fmaf(qs[d + 2], kv4.z, a0);
            a1 = fmaf(qs[d + 3], kv4.w, a1);
        }
        float lg = (a0 + a1) * 0.125f
                 + biasT[(((size_t)b * NHEAD + h) * NSEQ + i) * NSEQ + j];
        if (mask[((size_t)(b * NSEQ + i)) * NSEQ + j] == 0) lg = -1e30f;
        lv[u] = lg;
    }

    int wid = tid >> 5, lane = tid & 31;
    float m = warp_max(fmaxf(lv[0], lv[1]));
    if (!lane) red[wid] = m;
    __syncthreads();
    m = fmaxf(fmaxf(red[0], red[1]), fmaxf(red[2], red[3]));
    __syncthreads();                     // red reuse below

    float e0 = __expf(lv[0] - m), e1 = __expf(lv[1] - m);
    ps[tid] = e0; ps[tid + 128] = e1;
    float s = warp_sum(e0 + e1);
    if (!lane) red[wid] = s;
    __syncthreads();
    float inv = 1.f / (red[0] + red[1] + red[2] + red[3]);

    int d = tid & 63, pr = tid >> 6;
    const float* vp = qkv + 2 * DMODEL + (size_t)h * HDIM + d;
    float a0 = 0.f, a1 = 0.f;
    int j0 = pr << 7;
    #pragma unroll 4
    for (int j = j0; j < j0 + 128; j += 2) {
        a0 = fmaf(ps[j],     vp[((size_t)(b * NSEQ + j)) * 2304],     a0);
        a1 = fmaf(ps[j + 1], vp[((size_t)(b * NSEQ + j + 1)) * 2304], a1);
    }
    part[pr][d] = a0 + a1;
    __syncthreads();
    if (tid < 64)
        ctx[((size_t)(b * NSEQ + i)) * DMODEL + h * HDIM + tid] =
            (part[0][tid] + part[1][tid]) * inv;
}

// ---------------- a = ctx * sigmoid(gated) ----------------
__global__ __launch_bounds__(256) void gate_mul_kernel(
    const float* __restrict__ ctx, const float* __restrict__ gated,
    float* __restrict__ a, int n)
{
    int idx = blockIdx.x * 256 + threadIdx.x;
    if (idx < n) {
        float g = gated[idx];
        a[idx] = ctx[idx] * (1.f / (1.f + __expf(-g)));
    }
}

// ---------------- launch ----------------
extern "C" void kernel_launch(void* const* d_in, const int* in_sizes, int n_in,
                              void* d_out, int out_size)
{
    const float* x       = (const float*)d_in[0];
    const float* dist    = (const float*)d_in[1];
    const int*   mask    = (const int*)  d_in[2];
    const float* qkv_w   = (const float*)d_in[3];
    const float* qkv_b   = (const float*)d_in[4];
    const float* out_w   = (const float*)d_in[5];
    const float* out_b   = (const float*)d_in[6];
    const float* rb_w1   = (const float*)d_in[7];
    const float* rb_b1   = (const float*)d_in[8];
    const float* rb_w2   = (const float*)d_in[9];
    const float* rb_b2   = (const float*)d_in[10];
    const float* gate_w1 = (const float*)d_in[11];
    const float* gate_b1 = (const float*)d_in[12];
    const float* gate_w2 = (const float*)d_in[13];
    const float* gate_b2 = (const float*)d_in[14];
    const float* ff_w1   = (const float*)d_in[15];
    const float* ff_b1   = (const float*)d_in[16];
    const float* ff_w2   = (const float*)d_in[17];
    const float* ff_b2   = (const float*)d_in[18];
    const float* ln1_g   = (const float*)d_in[19];
    const float* ln1_b   = (const float*)d_in[20];
    const float* ln2_g   = (const float*)d_in[21];
    const float* ln2_b   = (const float*)d_in[22];
    float* out = (float*)d_out;

    float *xn, *qkv, *s1, *gated, *biasT, *ctx, *a, *x2, *y, *ffh;
    cudaGetSymbolAddress((void**)&xn,    g_xn);
    cudaGetSymbolAddress((void**)&qkv,   g_qkv);
    cudaGetSymbolAddress((void**)&s1,    g_s1);
    cudaGetSymbolAddress((void**)&gated, g_gated);
    cudaGetSymbolAddress((void**)&biasT, g_biasT);
    cudaGetSymbolAddress((void**)&ctx,   g_ctx);
    cudaGetSymbolAddress((void**)&a,     g_a);
    cudaGetSymbolAddress((void**)&x2,    g_x2);
    cudaGetSymbolAddress((void**)&y,     g_y);
    cudaGetSymbolAddress((void**)&ffh,   g_ffh);

    // one-time side-stream + events (created on the uncaptured correctness
    // call; reused inside graph capture thereafter — no device allocations)
    static cudaStream_t s2 = nullptr;
    static cudaEvent_t evFork = nullptr, evJoin = nullptr;
    if (!s2) {
        cudaStreamCreateWithFlags(&s2, cudaStreamNonBlocking);
        cudaEventCreateWithFlags(&evFork, cudaEventDisableTiming);
        cudaEventCreateWithFlags(&evJoin, cudaEventDisableTiming);
    }

    // fork: rbias (dist-only dependency, ~half the total work) runs on s2,
    // overlapping ln1 -> qkv -> s1 on the main stream
    cudaEventRecord(evFork, 0);
    cudaStreamWaitEvent(s2, evFork, 0);
    rbias_mma_kernel<<<MROWS, 256, 0, s2>>>(dist, rb_w1, rb_b1, rb_w2, rb_b2, biasT);
    cudaEventRecord(evJoin, s2);

    // main stream: LN1 -> qkv -> s1 (independent of rbias)
    ln_kernel<<<MROWS, 256>>>(x, ln1_g, ln1_b, xn);
    gemm_kernel<0, false><<<dim3(36, 16), 256>>>(xn, qkv_w, qkv_b, nullptr, qkv,
                                                 MROWS, 3 * DMODEL, DMODEL);
    gemm_kernel<1, false><<<dim3(12, 16), 256>>>(xn, gate_w1, gate_b1, nullptr, s1,
                                                 MROWS, DMODEL, DMODEL);
    // gated = s1 @ gate_w2 + b (also independent of rbias/attn)
    gemm_kernel<0, false><<<dim3(12, 16), 256>>>(s1, gate_w2, gate_b2, nullptr, gated,
                                                 MROWS, DMODEL, DMODEL);

    // join: attention needs qkv AND biasT
    cudaStreamWaitEvent(0, evJoin, 0);
    attn_kernel<<<dim3(NSEQ, NHEAD, 4), 128>>>(qkv, biasT, mask, ctx);
    // a = ctx * sigmoid(gated)
    gate_mul_kernel<<<(MROWS * DMODEL + 255) / 256, 256>>>(ctx, gated, a, MROWS * DMODEL);
    // x2 = x + a @ out_w + out_b
    gemm_kernel<0, true><<<dim3(12, 16), 256>>>(a, out_w, out_b, x, x2,
                                                MROWS, DMODEL, DMODEL);
    // LN2
    ln_kernel<<<MROWS, 256>>>(x2, ln2_g, ln2_b, y);
    // ffh = gelu(y @ ff_w1 + b)
    gemm_kernel<2, false><<<dim3(24, 16), 256>>>(y, ff_w1, ff_b1, nullptr, ffh,
                                                 MROWS, 2 * DMODEL, DMODEL);
    // out = x2 + ffh @ ff_w2 + b
    gemm_kernel<0, true><<<dim3(12, 16), 256>>>(ffh, ff_w2, ff_b2, x2, out,
                                                MROWS, DMODEL, 2 * DMODEL);
}